// round 13
// baseline (speedup 1.0000x reference)
#include <cuda_runtime.h>
#include <cuda_bf16.h>
#include <cuda_fp16.h>
#include <math.h>

// Problem constants (fixed by the dataset)
#define MAXN 25000
#define MAXE 400000
#define IN_DIM 128
#define H_DIM 4
#define F_DIM 64
#define HF 256          // H*F
#define HIN 512         // H*IN

#define NEG_SLOPE 0.2f
#define SCAN_BLK 256
#define EPW 16          // edges (CSR positions) per warp in tail edge phase

// ---------------- device scratch (no allocations allowed) ----------------
__device__ __align__(16) float g_wl[H_DIM * IN_DIM];   // folded attn_l @ W
__device__ __align__(16) float g_wr[H_DIM * IN_DIM];   // folded attn_r @ W
__device__ __align__(16) float g_el[MAXN * H_DIM];
__device__ __align__(16) float g_er[MAXN * H_DIM];
__device__ __align__(16) float  g_agg[(size_t)MAXN * HIN];    // 51.2 MB fp32
__device__ __align__(16) __half g_aggh[(size_t)MAXN * HIN];   // 25.6 MB fp16 mirror
__device__ int       g_count[MAXN];
__device__ int       g_off[MAXN + 1];
__device__ int       g_cursor[MAXN];
__device__ long long g_es[MAXE];     // packed (src<<32 | eid) in CSR order
__device__ int       g_dsts[MAXE];   // dst node id per CSR position
__device__ int       g_part[(MAXN + SCAN_BLK - 1) / SCAN_BLK + 1];

__device__ __forceinline__ float lrelu(float x) {
    return x > 0.0f ? x : NEG_SLOPE * x;
}

// ---------------- 0. prep (fold attn into W) + zero counts ------------------
__global__ void prep_zero_kernel(const float* __restrict__ Wm,
                                 const float* __restrict__ attn_l,
                                 const float* __restrict__ attn_r, int N)
{
    if (blockIdx.x < 2) {
        int t = blockIdx.x * 256 + threadIdx.x;   // 0..511
        if (t >= H_DIM * IN_DIM) return;
        int h = t >> 7, i = t & 127;
        float sl = 0.f, sr = 0.f;
        const float* wbase = Wm + (size_t)h * F_DIM * IN_DIM + i;
#pragma unroll 16
        for (int f = 0; f < F_DIM; f++) {
            float w = wbase[(size_t)f * IN_DIM];
            sl += attn_l[h * F_DIM + f] * w;
            sr += attn_r[h * F_DIM + f] * w;
        }
        g_wl[t] = sl;
        g_wr[t] = sr;
    } else {
        int i = (blockIdx.x - 2) * 256 + threadIdx.x;
        if (i < N) g_count[i] = 0;
    }
}

// ---------------- 1. el/er per node + dst histogram (independent works) ------
__global__ void elr_hist_kernel(const float* __restrict__ feat,
                                const int* __restrict__ dst,
                                int N, int E, int ELR_B)
{
    if (blockIdx.x < ELR_B) {
        int w = (blockIdx.x * blockDim.x + threadIdx.x) >> 5;
        int lane = threadIdx.x & 31;
        if (w >= N) return;
        float4 fv = *(const float4*)&feat[(size_t)w * IN_DIM + lane * 4];
        float sl[4], sr[4];
#pragma unroll
        for (int h = 0; h < 4; h++) {
            float4 a = *(const float4*)&g_wl[h * IN_DIM + lane * 4];
            float4 b = *(const float4*)&g_wr[h * IN_DIM + lane * 4];
            sl[h] = fv.x * a.x + fv.y * a.y + fv.z * a.z + fv.w * a.w;
            sr[h] = fv.x * b.x + fv.y * b.y + fv.z * b.z + fv.w * b.w;
        }
#pragma unroll
        for (int o = 16; o; o >>= 1) {
#pragma unroll
            for (int h = 0; h < 4; h++) {
                sl[h] += __shfl_xor_sync(0xffffffffu, sl[h], o);
                sr[h] += __shfl_xor_sync(0xffffffffu, sr[h], o);
            }
        }
        if (lane == 0) {
            *(float4*)&g_el[w * 4] = make_float4(sl[0], sl[1], sl[2], sl[3]);
            *(float4*)&g_er[w * 4] = make_float4(sr[0], sr[1], sr[2], sr[3]);
        }
    } else {
        int e = (blockIdx.x - ELR_B) * blockDim.x + threadIdx.x;
        if (e < E) atomicAdd(&g_count[dst[e]], 1);
    }
}

// ---------------- 2. hierarchical scan (2 kernels) + scatter -----------------
__global__ void part_sum_kernel(int N) {
    __shared__ int sh[SCAN_BLK];
    int i = blockIdx.x * SCAN_BLK + threadIdx.x;
    sh[threadIdx.x] = (i < N) ? g_count[i] : 0;
    __syncthreads();
#pragma unroll
    for (int d = SCAN_BLK / 2; d; d >>= 1) {
        if (threadIdx.x < d) sh[threadIdx.x] += sh[threadIdx.x + d];
        __syncthreads();
    }
    if (threadIdx.x == 0) g_part[blockIdx.x] = sh[0];
}
__global__ void offsets_kernel(int N, int E, int NB) {
    __shared__ int part[128];
    __shared__ int sh[SCAN_BLK];
    int t = threadIdx.x;
    if (t < 128) part[t] = (t < NB) ? g_part[t] : 0;
    __syncthreads();
    for (int d = 1; d < 128; d <<= 1) {
        int u = (t < 128 && t >= d) ? part[t - d] : 0;
        __syncthreads();
        if (t < 128) part[t] += u;
        __syncthreads();
    }
    int base = (blockIdx.x == 0) ? 0 : part[blockIdx.x - 1];

    int i = blockIdx.x * SCAN_BLK + t;
    int v = (i < N) ? g_count[i] : 0;
    sh[t] = v;
    __syncthreads();
    for (int d = 1; d < SCAN_BLK; d <<= 1) {
        int u = (t >= d) ? sh[t - d] : 0;
        __syncthreads();
        sh[t] += u;
        __syncthreads();
    }
    int off = base + sh[t] - v;
    if (i < N) { g_off[i] = off; g_cursor[i] = off; }
    if (blockIdx.x == 0 && t == 0) g_off[N] = E;
}
__global__ void scatter_kernel(const int* __restrict__ src,
                               const int* __restrict__ dst, int E) {
    int e = blockIdx.x * blockDim.x + threadIdx.x;
    if (e < E) {
        int s = src[e];
        int d = dst[e];
        int pos = atomicAdd(&g_cursor[d], 1);
        g_es[pos] = ((long long)s << 32) | (unsigned)e;
        g_dsts[pos] = d;
    }
}

// ---------------- 3. per-dst-node softmax + agg_ori aggregation --------------
__global__ __launch_bounds__(256) void agg_kernel(
    const float* __restrict__ feat, int N)
{
    int w = (blockIdx.x * blockDim.x + threadIdx.x) >> 5;
    int lane = threadIdx.x & 31;
    if (w >= N) return;
    int n = w;
    int start = g_off[n];
    int deg = g_off[n + 1] - start;

    if (deg == 0) {
#pragma unroll
        for (int h = 0; h < H_DIM; h++) {
            *(float4*)&g_agg[(size_t)n * HIN + h * IN_DIM + lane * 4] =
                make_float4(0.f, 0.f, 0.f, 0.f);
            *(uint2*)&g_aggh[(size_t)n * HIN + h * IN_DIM + lane * 4] =
                make_uint2(0u, 0u);
        }
        return;
    }

    float4 er4 = *(const float4*)&g_er[n * 4];

    int mysrc = 0;
    float e0 = -1e30f, e1 = -1e30f, e2 = -1e30f, e3 = -1e30f;
    if (lane < deg) {
        mysrc = (int)(g_es[start + lane] >> 32);
        float4 el4 = *(const float4*)&g_el[mysrc * 4];
        e0 = lrelu(el4.x + er4.x); e1 = lrelu(el4.y + er4.y);
        e2 = lrelu(el4.z + er4.z); e3 = lrelu(el4.w + er4.w);
    }
    float m0 = e0, m1 = e1, m2 = e2, m3 = e3;
    for (int j = 32 + lane; j < deg; j += 32) {
        int s = (int)(g_es[start + j] >> 32);
        float4 el4 = *(const float4*)&g_el[s * 4];
        m0 = fmaxf(m0, lrelu(el4.x + er4.x)); m1 = fmaxf(m1, lrelu(el4.y + er4.y));
        m2 = fmaxf(m2, lrelu(el4.z + er4.z)); m3 = fmaxf(m3, lrelu(el4.w + er4.w));
    }
#pragma unroll
    for (int o = 16; o; o >>= 1) {
        m0 = fmaxf(m0, __shfl_xor_sync(0xffffffffu, m0, o));
        m1 = fmaxf(m1, __shfl_xor_sync(0xffffffffu, m1, o));
        m2 = fmaxf(m2, __shfl_xor_sync(0xffffffffu, m2, o));
        m3 = fmaxf(m3, __shfl_xor_sync(0xffffffffu, m3, o));
    }

    float aO[4][4] = {};
    float s0 = 0.f, s1 = 0.f, s2 = 0.f, s3 = 0.f;

    int dmain = min(deg, 32);
    int sj = __shfl_sync(0xffffffffu, mysrc, 0);
    float4 fv_n = *(const float4*)&feat[(size_t)sj * IN_DIM + lane * 4];
    for (int j = 0; j < dmain; j++) {
        float4 fv = fv_n;
        if (j + 1 < dmain) {
            int sn = __shfl_sync(0xffffffffu, mysrc, j + 1);
            fv_n = *(const float4*)&feat[(size_t)sn * IN_DIM + lane * 4];
        }
        float ex0 = __expf(__shfl_sync(0xffffffffu, e0, j) - m0);
        float ex1 = __expf(__shfl_sync(0xffffffffu, e1, j) - m1);
        float ex2 = __expf(__shfl_sync(0xffffffffu, e2, j) - m2);
        float ex3 = __expf(__shfl_sync(0xffffffffu, e3, j) - m3);
        s0 += ex0; s1 += ex1; s2 += ex2; s3 += ex3;
        aO[0][0] += ex0 * fv.x; aO[0][1] += ex0 * fv.y; aO[0][2] += ex0 * fv.z; aO[0][3] += ex0 * fv.w;
        aO[1][0] += ex1 * fv.x; aO[1][1] += ex1 * fv.y; aO[1][2] += ex1 * fv.z; aO[1][3] += ex1 * fv.w;
        aO[2][0] += ex2 * fv.x; aO[2][1] += ex2 * fv.y; aO[2][2] += ex2 * fv.z; aO[2][3] += ex2 * fv.w;
        aO[3][0] += ex3 * fv.x; aO[3][1] += ex3 * fv.y; aO[3][2] += ex3 * fv.z; aO[3][3] += ex3 * fv.w;
    }
    for (int j = 32; j < deg; j++) {
        int s = (int)(g_es[start + j] >> 32);
        float4 el4 = *(const float4*)&g_el[s * 4];
        float ex0 = __expf(lrelu(el4.x + er4.x) - m0);
        float ex1 = __expf(lrelu(el4.y + er4.y) - m1);
        float ex2 = __expf(lrelu(el4.z + er4.z) - m2);
        float ex3 = __expf(lrelu(el4.w + er4.w) - m3);
        s0 += ex0; s1 += ex1; s2 += ex2; s3 += ex3;
        float4 fv = *(const float4*)&feat[(size_t)s * IN_DIM + lane * 4];
        aO[0][0] += ex0 * fv.x; aO[0][1] += ex0 * fv.y; aO[0][2] += ex0 * fv.z; aO[0][3] += ex0 * fv.w;
        aO[1][0] += ex1 * fv.x; aO[1][1] += ex1 * fv.y; aO[1][2] += ex1 * fv.z; aO[1][3] += ex1 * fv.w;
        aO[2][0] += ex2 * fv.x; aO[2][1] += ex2 * fv.y; aO[2][2] += ex2 * fv.z; aO[2][3] += ex2 * fv.w;
        aO[3][0] += ex3 * fv.x; aO[3][1] += ex3 * fv.y; aO[3][2] += ex3 * fv.z; aO[3][3] += ex3 * fv.w;
    }

    float inv[4] = { 1.0f / s0, 1.0f / s1, 1.0f / s2, 1.0f / s3 };
#pragma unroll
    for (int h = 0; h < 4; h++) {
        float4 v = make_float4(aO[h][0] * inv[h], aO[h][1] * inv[h],
                               aO[h][2] * inv[h], aO[h][3] * inv[h]);
        *(float4*)&g_agg[(size_t)n * HIN + h * IN_DIM + lane * 4] = v;
        __half2 h01 = __floats2half2_rn(v.x, v.y);
        __half2 h23 = __floats2half2_rn(v.z, v.w);
        uint2 raw;
        raw.x = *(unsigned*)&h01;
        raw.y = *(unsigned*)&h23;
        *(uint2*)&g_aggh[(size_t)n * HIN + h * IN_DIM + lane * 4] = raw;
    }
}

// ---------------- 4. fused tail: rst GEMM blocks + edge_out blocks -----------
// Edge phase is edge-balanced: one warp per EPW consecutive CSR positions.
// Lane owns 16 contiguous elements of the 512-float row: src = 2x LDG.128
// fp16, dst cached fp32 (reloaded on node-boundary crossings), out = 4x
// STG.128 streaming.
__global__ __launch_bounds__(256) void tail_kernel(
    const float* __restrict__ Wm, float* __restrict__ rst,
    float* __restrict__ out, int N, int E, int GB)
{
    __shared__ float As[32][68];   // [k][node]
    __shared__ float Bs[32][68];   // [k][f]

    if (blockIdx.x < GB) {
        int t = threadIdx.x;
        int row0 = (blockIdx.x >> 2) * 64;
        int h = blockIdx.x & 3;
        int ty = t >> 4, tx = t & 15;
        float acc[4][4] = {};

        const float* Arow = g_agg + (size_t)h * IN_DIM;          // + n*HIN
        const float* Brow = Wm + (size_t)h * F_DIM * IN_DIM;     // + f*IN_DIM

        for (int kt = 0; kt < 4; kt++) {
#pragma unroll
            for (int i = 0; i < 2; i++) {
                int idx = t + i * 256;     // 0..511
                int r = idx >> 3;          // 0..63
                int k4 = idx & 7;          // 0..7
                int row = row0 + r;
                float4 v = make_float4(0.f, 0.f, 0.f, 0.f);
                if (row < N) v = *(const float4*)&Arow[(size_t)row * HIN + kt * 32 + k4 * 4];
                As[k4 * 4 + 0][r] = v.x; As[k4 * 4 + 1][r] = v.y;
                As[k4 * 4 + 2][r] = v.z; As[k4 * 4 + 3][r] = v.w;
                float4 wv = *(const float4*)&Brow[(size_t)r * IN_DIM + kt * 32 + k4 * 4];
                Bs[k4 * 4 + 0][r] = wv.x; Bs[k4 * 4 + 1][r] = wv.y;
                Bs[k4 * 4 + 2][r] = wv.z; Bs[k4 * 4 + 3][r] = wv.w;
            }
            __syncthreads();
#pragma unroll 8
            for (int k = 0; k < 32; k++) {
                float4 a = *(const float4*)&As[k][ty * 4];
                float4 b = *(const float4*)&Bs[k][tx * 4];
                acc[0][0] += a.x * b.x; acc[0][1] += a.x * b.y; acc[0][2] += a.x * b.z; acc[0][3] += a.x * b.w;
                acc[1][0] += a.y * b.x; acc[1][1] += a.y * b.y; acc[1][2] += a.y * b.z; acc[1][3] += a.y * b.w;
                acc[2][0] += a.z * b.x; acc[2][1] += a.z * b.y; acc[2][2] += a.z * b.z; acc[2][3] += a.z * b.w;
                acc[3][0] += a.w * b.x; acc[3][1] += a.w * b.y; acc[3][2] += a.w * b.z; acc[3][3] += a.w * b.w;
            }
            __syncthreads();
        }
#pragma unroll
        for (int i = 0; i < 4; i++) {
            int row = row0 + ty * 4 + i;
            if (row < N) {
                float4 v = make_float4(fmaxf(acc[i][0], 0.f), fmaxf(acc[i][1], 0.f),
                                       fmaxf(acc[i][2], 0.f), fmaxf(acc[i][3], 0.f));
                __stcs((float4*)&rst[(size_t)row * HF + h * F_DIM + tx * 4], v);
            }
        }
        return;
    }

    // ---- edge_out part: edge-balanced chunks ----
    int gw = ((blockIdx.x - GB) * blockDim.x + threadIdx.x) >> 5;
    int lane = threadIdx.x & 31;
    int p0 = gw * EPW;
    if (p0 >= E) return;
    int p1 = min(p0 + EPW, E);

    int curd = -1;
    float4 bd[4];

    long long es = g_es[p0];
    int d = g_dsts[p0];
    uint4 a0, a1;
    {
        int s = (int)(es >> 32);
        const uint4* ash = (const uint4*)&g_aggh[(size_t)s * HIN + lane * 16];
        a0 = ash[0]; a1 = ash[1];
    }
    for (int p = p0; p < p1; p++) {
        long long nes = 0; int nd = 0;
        uint4 n0, n1;
        if (p + 1 < p1) {
            nes = g_es[p + 1];
            nd = g_dsts[p + 1];
            int ns = (int)(nes >> 32);
            const uint4* asn = (const uint4*)&g_aggh[(size_t)ns * HIN + lane * 16];
            n0 = asn[0]; n1 = asn[1];
        }
        if (d != curd) {
            curd = d;
            const float4* ad = (const float4*)&g_agg[(size_t)curd * HIN + lane * 16];
            bd[0] = ad[0]; bd[1] = ad[1]; bd[2] = ad[2]; bd[3] = ad[3];
        }
        int eid = (int)es;
        float4* o = (float4*)&out[(size_t)eid * HIN + lane * 16];
        float2 f0 = __half22float2(*(__half2*)&a0.x);
        float2 f1 = __half22float2(*(__half2*)&a0.y);
        float2 f2 = __half22float2(*(__half2*)&a0.z);
        float2 f3 = __half22float2(*(__half2*)&a0.w);
        float2 f4 = __half22float2(*(__half2*)&a1.x);
        float2 f5 = __half22float2(*(__half2*)&a1.y);
        float2 f6 = __half22float2(*(__half2*)&a1.z);
        float2 f7 = __half22float2(*(__half2*)&a1.w);
        __stcs(&o[0], make_float4(fabsf(f0.x - bd[0].x), fabsf(f0.y - bd[0].y),
                                  fabsf(f1.x - bd[0].z), fabsf(f1.y - bd[0].w)));
        __stcs(&o[1], make_float4(fabsf(f2.x - bd[1].x), fabsf(f2.y - bd[1].y),
                                  fabsf(f3.x - bd[1].z), fabsf(f3.y - bd[1].w)));
        __stcs(&o[2], make_float4(fabsf(f4.x - bd[2].x), fabsf(f4.y - bd[2].y),
                                  fabsf(f5.x - bd[2].z), fabsf(f5.y - bd[2].w)));
        __stcs(&o[3], make_float4(fabsf(f6.x - bd[3].x), fabsf(f6.y - bd[3].y),
                                  fabsf(f7.x - bd[3].z), fabsf(f7.y - bd[3].w)));
        es = nes; d = nd; a0 = n0; a1 = n1;
    }
}

// ---------------- launch -----------------------------------------------------
extern "C" void kernel_launch(void* const* d_in, const int* in_sizes, int n_in,
                              void* d_out, int out_size)
{
    const float* feat   = (const float*)d_in[0];
    const float* Wm     = (const float*)d_in[1];
    const float* attn_l = (const float*)d_in[2];
    const float* attn_r = (const float*)d_in[3];
    const int*   src    = (const int*)d_in[4];
    const int*   dst    = (const int*)d_in[5];
    int N = in_sizes[0] / IN_DIM;
    int E = in_sizes[4];
    float* out = (float*)d_out;
    int NB = (N + SCAN_BLK - 1) / SCAN_BLK;

    // 0. prep + zero counts
    prep_zero_kernel<<<2 + (N + 255) / 256, 256>>>(Wm, attn_l, attn_r, N);
    // 1. elr + hist (independent)
    int ELR_B = (N * 32 + 255) / 256;
    int HIST_B = (E + 255) / 256;
    elr_hist_kernel<<<ELR_B + HIST_B, 256>>>(feat, dst, N, E, ELR_B);
    // 2. scan (2 launches) + scatter
    part_sum_kernel<<<NB, SCAN_BLK>>>(N);
    offsets_kernel<<<NB, SCAN_BLK>>>(N, E, NB);
    scatter_kernel<<<(E + 255) / 256, 256>>>(src, dst, E);
    // 3. softmax + agg_ori aggregation
    agg_kernel<<<(N * 32 + 255) / 256, 256>>>(feat, N);
    // 4. fused tail: rst GEMM + edge output (edge-balanced)
    int GB = ((N + 63) / 64) * 4;
    int NW = (E + EPW - 1) / EPW;              // edge warps
    int EB = (NW * 32 + 255) / 256;
    tail_kernel<<<GB + EB, 256>>>(Wm, out, out + (size_t)N * HF, N, E, GB);
}

// round 14
// speedup vs baseline: 1.3789x; 1.3789x over previous
#include <cuda_runtime.h>
#include <cuda_bf16.h>
#include <cuda_fp16.h>
#include <math.h>

// Problem constants (fixed by the dataset)
#define MAXN 25000
#define MAXE 400000
#define IN_DIM 128
#define H_DIM 4
#define F_DIM 64
#define HF 256          // H*F
#define HIN 512         // H*IN

#define NEG_SLOPE 0.2f
#define SCAN_BLK 256
#define EPW 16          // edges (CSR positions) per warp in tail edge phase

// ---------------- device scratch (no allocations allowed) ----------------
__device__ __align__(16) float g_wl[H_DIM * IN_DIM];   // folded attn_l @ W
__device__ __align__(16) float g_wr[H_DIM * IN_DIM];   // folded attn_r @ W
__device__ __align__(16) float g_el[MAXN * H_DIM];
__device__ __align__(16) float g_er[MAXN * H_DIM];
__device__ __align__(16) float  g_agg[(size_t)MAXN * HIN];    // 51.2 MB fp32
__device__ __align__(16) __half g_aggh[(size_t)MAXN * HIN];   // 25.6 MB fp16 mirror
__device__ int       g_count[MAXN];
__device__ int       g_off[MAXN + 1];
__device__ int       g_cursor[MAXN];
__device__ long long g_es[MAXE];     // packed (src<<32 | eid) in CSR order
__device__ int       g_dsts[MAXE];   // dst node id per CSR position
__device__ int       g_part[(MAXN + SCAN_BLK - 1) / SCAN_BLK + 1];

__device__ __forceinline__ float lrelu(float x) {
    return x > 0.0f ? x : NEG_SLOPE * x;
}

// ---------------- 0. prep (fold attn into W) + zero counts ------------------
__global__ void prep_zero_kernel(const float* __restrict__ Wm,
                                 const float* __restrict__ attn_l,
                                 const float* __restrict__ attn_r, int N)
{
    if (blockIdx.x < 2) {
        int t = blockIdx.x * 256 + threadIdx.x;   // 0..511
        if (t >= H_DIM * IN_DIM) return;
        int h = t >> 7, i = t & 127;
        float sl = 0.f, sr = 0.f;
        const float* wbase = Wm + (size_t)h * F_DIM * IN_DIM + i;
#pragma unroll 16
        for (int f = 0; f < F_DIM; f++) {
            float w = wbase[(size_t)f * IN_DIM];
            sl += attn_l[h * F_DIM + f] * w;
            sr += attn_r[h * F_DIM + f] * w;
        }
        g_wl[t] = sl;
        g_wr[t] = sr;
    } else {
        int i = (blockIdx.x - 2) * 256 + threadIdx.x;
        if (i < N) g_count[i] = 0;
    }
}

// ---------------- 1. el/er per node + dst histogram (independent works) ------
__global__ void elr_hist_kernel(const float* __restrict__ feat,
                                const int* __restrict__ dst,
                                int N, int E, int ELR_B)
{
    if (blockIdx.x < ELR_B) {
        int w = (blockIdx.x * blockDim.x + threadIdx.x) >> 5;
        int lane = threadIdx.x & 31;
        if (w >= N) return;
        float4 fv = *(const float4*)&feat[(size_t)w * IN_DIM + lane * 4];
        float sl[4], sr[4];
#pragma unroll
        for (int h = 0; h < 4; h++) {
            float4 a = *(const float4*)&g_wl[h * IN_DIM + lane * 4];
            float4 b = *(const float4*)&g_wr[h * IN_DIM + lane * 4];
            sl[h] = fv.x * a.x + fv.y * a.y + fv.z * a.z + fv.w * a.w;
            sr[h] = fv.x * b.x + fv.y * b.y + fv.z * b.z + fv.w * b.w;
        }
#pragma unroll
        for (int o = 16; o; o >>= 1) {
#pragma unroll
            for (int h = 0; h < 4; h++) {
                sl[h] += __shfl_xor_sync(0xffffffffu, sl[h], o);
                sr[h] += __shfl_xor_sync(0xffffffffu, sr[h], o);
            }
        }
        if (lane == 0) {
            *(float4*)&g_el[w * 4] = make_float4(sl[0], sl[1], sl[2], sl[3]);
            *(float4*)&g_er[w * 4] = make_float4(sr[0], sr[1], sr[2], sr[3]);
        }
    } else {
        int e = (blockIdx.x - ELR_B) * blockDim.x + threadIdx.x;
        if (e < E) atomicAdd(&g_count[dst[e]], 1);
    }
}

// ---------------- 2. hierarchical scan (2 kernels) + scatter -----------------
__global__ void part_sum_kernel(int N) {
    __shared__ int sh[SCAN_BLK];
    int i = blockIdx.x * SCAN_BLK + threadIdx.x;
    sh[threadIdx.x] = (i < N) ? g_count[i] : 0;
    __syncthreads();
#pragma unroll
    for (int d = SCAN_BLK / 2; d; d >>= 1) {
        if (threadIdx.x < d) sh[threadIdx.x] += sh[threadIdx.x + d];
        __syncthreads();
    }
    if (threadIdx.x == 0) g_part[blockIdx.x] = sh[0];
}
__global__ void offsets_kernel(int N, int E, int NB) {
    __shared__ int part[128];
    __shared__ int sh[SCAN_BLK];
    int t = threadIdx.x;
    if (t < 128) part[t] = (t < NB) ? g_part[t] : 0;
    __syncthreads();
    for (int d = 1; d < 128; d <<= 1) {
        int u = (t < 128 && t >= d) ? part[t - d] : 0;
        __syncthreads();
        if (t < 128) part[t] += u;
        __syncthreads();
    }
    int base = (blockIdx.x == 0) ? 0 : part[blockIdx.x - 1];

    int i = blockIdx.x * SCAN_BLK + t;
    int v = (i < N) ? g_count[i] : 0;
    sh[t] = v;
    __syncthreads();
    for (int d = 1; d < SCAN_BLK; d <<= 1) {
        int u = (t >= d) ? sh[t - d] : 0;
        __syncthreads();
        sh[t] += u;
        __syncthreads();
    }
    int off = base + sh[t] - v;
    if (i < N) { g_off[i] = off; g_cursor[i] = off; }
    if (blockIdx.x == 0 && t == 0) g_off[N] = E;
}
__global__ void scatter_kernel(const int* __restrict__ src,
                               const int* __restrict__ dst, int E) {
    int e = blockIdx.x * blockDim.x + threadIdx.x;
    if (e < E) {
        int s = src[e];
        int d = dst[e];
        int pos = atomicAdd(&g_cursor[d], 1);
        g_es[pos] = ((long long)s << 32) | (unsigned)e;
        g_dsts[pos] = d;
    }
}

// ---------------- 3. per-dst-node softmax + agg_ori aggregation --------------
__global__ __launch_bounds__(256) void agg_kernel(
    const float* __restrict__ feat, int N)
{
    int w = (blockIdx.x * blockDim.x + threadIdx.x) >> 5;
    int lane = threadIdx.x & 31;
    if (w >= N) return;
    int n = w;
    int start = g_off[n];
    int deg = g_off[n + 1] - start;

    if (deg == 0) {
#pragma unroll
        for (int h = 0; h < H_DIM; h++) {
            *(float4*)&g_agg[(size_t)n * HIN + h * IN_DIM + lane * 4] =
                make_float4(0.f, 0.f, 0.f, 0.f);
            *(uint2*)&g_aggh[(size_t)n * HIN + h * IN_DIM + lane * 4] =
                make_uint2(0u, 0u);
        }
        return;
    }

    float4 er4 = *(const float4*)&g_er[n * 4];

    int mysrc = 0;
    float e0 = -1e30f, e1 = -1e30f, e2 = -1e30f, e3 = -1e30f;
    if (lane < deg) {
        mysrc = (int)(g_es[start + lane] >> 32);
        float4 el4 = *(const float4*)&g_el[mysrc * 4];
        e0 = lrelu(el4.x + er4.x); e1 = lrelu(el4.y + er4.y);
        e2 = lrelu(el4.z + er4.z); e3 = lrelu(el4.w + er4.w);
    }
    float m0 = e0, m1 = e1, m2 = e2, m3 = e3;
    for (int j = 32 + lane; j < deg; j += 32) {
        int s = (int)(g_es[start + j] >> 32);
        float4 el4 = *(const float4*)&g_el[s * 4];
        m0 = fmaxf(m0, lrelu(el4.x + er4.x)); m1 = fmaxf(m1, lrelu(el4.y + er4.y));
        m2 = fmaxf(m2, lrelu(el4.z + er4.z)); m3 = fmaxf(m3, lrelu(el4.w + er4.w));
    }
#pragma unroll
    for (int o = 16; o; o >>= 1) {
        m0 = fmaxf(m0, __shfl_xor_sync(0xffffffffu, m0, o));
        m1 = fmaxf(m1, __shfl_xor_sync(0xffffffffu, m1, o));
        m2 = fmaxf(m2, __shfl_xor_sync(0xffffffffu, m2, o));
        m3 = fmaxf(m3, __shfl_xor_sync(0xffffffffu, m3, o));
    }

    float aO[4][4] = {};
    float s0 = 0.f, s1 = 0.f, s2 = 0.f, s3 = 0.f;

    int dmain = min(deg, 32);
    int sj = __shfl_sync(0xffffffffu, mysrc, 0);
    float4 fv_n = *(const float4*)&feat[(size_t)sj * IN_DIM + lane * 4];
    for (int j = 0; j < dmain; j++) {
        float4 fv = fv_n;
        if (j + 1 < dmain) {
            int sn = __shfl_sync(0xffffffffu, mysrc, j + 1);
            fv_n = *(const float4*)&feat[(size_t)sn * IN_DIM + lane * 4];
        }
        float ex0 = __expf(__shfl_sync(0xffffffffu, e0, j) - m0);
        float ex1 = __expf(__shfl_sync(0xffffffffu, e1, j) - m1);
        float ex2 = __expf(__shfl_sync(0xffffffffu, e2, j) - m2);
        float ex3 = __expf(__shfl_sync(0xffffffffu, e3, j) - m3);
        s0 += ex0; s1 += ex1; s2 += ex2; s3 += ex3;
        aO[0][0] += ex0 * fv.x; aO[0][1] += ex0 * fv.y; aO[0][2] += ex0 * fv.z; aO[0][3] += ex0 * fv.w;
        aO[1][0] += ex1 * fv.x; aO[1][1] += ex1 * fv.y; aO[1][2] += ex1 * fv.z; aO[1][3] += ex1 * fv.w;
        aO[2][0] += ex2 * fv.x; aO[2][1] += ex2 * fv.y; aO[2][2] += ex2 * fv.z; aO[2][3] += ex2 * fv.w;
        aO[3][0] += ex3 * fv.x; aO[3][1] += ex3 * fv.y; aO[3][2] += ex3 * fv.z; aO[3][3] += ex3 * fv.w;
    }
    for (int j = 32; j < deg; j++) {
        int s = (int)(g_es[start + j] >> 32);
        float4 el4 = *(const float4*)&g_el[s * 4];
        float ex0 = __expf(lrelu(el4.x + er4.x) - m0);
        float ex1 = __expf(lrelu(el4.y + er4.y) - m1);
        float ex2 = __expf(lrelu(el4.z + er4.z) - m2);
        float ex3 = __expf(lrelu(el4.w + er4.w) - m3);
        s0 += ex0; s1 += ex1; s2 += ex2; s3 += ex3;
        float4 fv = *(const float4*)&feat[(size_t)s * IN_DIM + lane * 4];
        aO[0][0] += ex0 * fv.x; aO[0][1] += ex0 * fv.y; aO[0][2] += ex0 * fv.z; aO[0][3] += ex0 * fv.w;
        aO[1][0] += ex1 * fv.x; aO[1][1] += ex1 * fv.y; aO[1][2] += ex1 * fv.z; aO[1][3] += ex1 * fv.w;
        aO[2][0] += ex2 * fv.x; aO[2][1] += ex2 * fv.y; aO[2][2] += ex2 * fv.z; aO[2][3] += ex2 * fv.w;
        aO[3][0] += ex3 * fv.x; aO[3][1] += ex3 * fv.y; aO[3][2] += ex3 * fv.z; aO[3][3] += ex3 * fv.w;
    }

    float inv[4] = { 1.0f / s0, 1.0f / s1, 1.0f / s2, 1.0f / s3 };
#pragma unroll
    for (int h = 0; h < 4; h++) {
        float4 v = make_float4(aO[h][0] * inv[h], aO[h][1] * inv[h],
                               aO[h][2] * inv[h], aO[h][3] * inv[h]);
        *(float4*)&g_agg[(size_t)n * HIN + h * IN_DIM + lane * 4] = v;
        __half2 h01 = __floats2half2_rn(v.x, v.y);
        __half2 h23 = __floats2half2_rn(v.z, v.w);
        uint2 raw;
        raw.x = *(unsigned*)&h01;
        raw.y = *(unsigned*)&h23;
        *(uint2*)&g_aggh[(size_t)n * HIN + h * IN_DIM + lane * 4] = raw;
    }
}

// ---------------- 4. fused tail: rst GEMM blocks + edge_out blocks -----------
// Edge phase: edge-balanced (one warp per EPW consecutive CSR positions) with
// the R12 interleaved lane layout (lane owns [h*128 + lane*4] per head) so all
// LDG/STG stay fully coalesced. dst row cached, reloaded on node boundary.
__global__ __launch_bounds__(256) void tail_kernel(
    const float* __restrict__ Wm, float* __restrict__ rst,
    float* __restrict__ out, int N, int E, int GB)
{
    __shared__ float As[32][68];   // [k][node]
    __shared__ float Bs[32][68];   // [k][f]

    if (blockIdx.x < GB) {
        int t = threadIdx.x;
        int row0 = (blockIdx.x >> 2) * 64;
        int h = blockIdx.x & 3;
        int ty = t >> 4, tx = t & 15;
        float acc[4][4] = {};

        const float* Arow = g_agg + (size_t)h * IN_DIM;          // + n*HIN
        const float* Brow = Wm + (size_t)h * F_DIM * IN_DIM;     // + f*IN_DIM

        for (int kt = 0; kt < 4; kt++) {
#pragma unroll
            for (int i = 0; i < 2; i++) {
                int idx = t + i * 256;     // 0..511
                int r = idx >> 3;          // 0..63
                int k4 = idx & 7;          // 0..7
                int row = row0 + r;
                float4 v = make_float4(0.f, 0.f, 0.f, 0.f);
                if (row < N) v = *(const float4*)&Arow[(size_t)row * HIN + kt * 32 + k4 * 4];
                As[k4 * 4 + 0][r] = v.x; As[k4 * 4 + 1][r] = v.y;
                As[k4 * 4 + 2][r] = v.z; As[k4 * 4 + 3][r] = v.w;
                float4 wv = *(const float4*)&Brow[(size_t)r * IN_DIM + kt * 32 + k4 * 4];
                Bs[k4 * 4 + 0][r] = wv.x; Bs[k4 * 4 + 1][r] = wv.y;
                Bs[k4 * 4 + 2][r] = wv.z; Bs[k4 * 4 + 3][r] = wv.w;
            }
            __syncthreads();
#pragma unroll 8
            for (int k = 0; k < 32; k++) {
                float4 a = *(const float4*)&As[k][ty * 4];
                float4 b = *(const float4*)&Bs[k][tx * 4];
                acc[0][0] += a.x * b.x; acc[0][1] += a.x * b.y; acc[0][2] += a.x * b.z; acc[0][3] += a.x * b.w;
                acc[1][0] += a.y * b.x; acc[1][1] += a.y * b.y; acc[1][2] += a.y * b.z; acc[1][3] += a.y * b.w;
                acc[2][0] += a.z * b.x; acc[2][1] += a.z * b.y; acc[2][2] += a.z * b.z; acc[2][3] += a.z * b.w;
                acc[3][0] += a.w * b.x; acc[3][1] += a.w * b.y; acc[3][2] += a.w * b.z; acc[3][3] += a.w * b.w;
            }
            __syncthreads();
        }
#pragma unroll
        for (int i = 0; i < 4; i++) {
            int row = row0 + ty * 4 + i;
            if (row < N) {
                float4 v = make_float4(fmaxf(acc[i][0], 0.f), fmaxf(acc[i][1], 0.f),
                                       fmaxf(acc[i][2], 0.f), fmaxf(acc[i][3], 0.f));
                __stcs((float4*)&rst[(size_t)row * HF + h * F_DIM + tx * 4], v);
            }
        }
        return;
    }

    // ---- edge_out part: edge-balanced chunks, interleaved lane layout ----
    int gw = ((blockIdx.x - GB) * blockDim.x + threadIdx.x) >> 5;
    int lane = threadIdx.x & 31;
    int p0 = gw * EPW;
    if (p0 >= E) return;
    int p1 = min(p0 + EPW, E);

    int curd = -1;
    float4 bd[4];

    long long es = g_es[p0];
    int d = g_dsts[p0];
    uint2 a[4];
    {
        int s = (int)(es >> 32);
        const uint2* ash = (const uint2*)&g_aggh[(size_t)s * HIN];
#pragma unroll
        for (int h = 0; h < 4; h++) a[h] = ash[h * 32 + lane];
    }
    for (int p = p0; p < p1; p++) {
        long long nes = 0; int nd = 0;
        uint2 nx[4];
        if (p + 1 < p1) {
            nes = g_es[p + 1];
            nd = g_dsts[p + 1];
            int ns = (int)(nes >> 32);
            const uint2* asn = (const uint2*)&g_aggh[(size_t)ns * HIN];
#pragma unroll
            for (int h = 0; h < 4; h++) nx[h] = asn[h * 32 + lane];
        }
        if (d != curd) {
            curd = d;
            const float4* ad = (const float4*)&g_agg[(size_t)curd * HIN];
#pragma unroll
            for (int h = 0; h < 4; h++) bd[h] = ad[h * 32 + lane];
        }
        int eid = (int)es;
        float4* o = (float4*)&out[(size_t)eid * HIN];
#pragma unroll
        for (int h = 0; h < 4; h++) {
            float2 f01 = __half22float2(*(__half2*)&a[h].x);
            float2 f23 = __half22float2(*(__half2*)&a[h].y);
            float4 v = make_float4(fabsf(f01.x - bd[h].x), fabsf(f01.y - bd[h].y),
                                   fabsf(f23.x - bd[h].z), fabsf(f23.y - bd[h].w));
            __stcs(&o[h * 32 + lane], v);
        }
        es = nes; d = nd;
#pragma unroll
        for (int h = 0; h < 4; h++) a[h] = nx[h];
    }
}

// ---------------- launch -----------------------------------------------------
extern "C" void kernel_launch(void* const* d_in, const int* in_sizes, int n_in,
                              void* d_out, int out_size)
{
    const float* feat   = (const float*)d_in[0];
    const float* Wm     = (const float*)d_in[1];
    const float* attn_l = (const float*)d_in[2];
    const float* attn_r = (const float*)d_in[3];
    const int*   src    = (const int*)d_in[4];
    const int*   dst    = (const int*)d_in[5];
    int N = in_sizes[0] / IN_DIM;
    int E = in_sizes[4];
    float* out = (float*)d_out;
    int NB = (N + SCAN_BLK - 1) / SCAN_BLK;

    // 0. prep + zero counts
    prep_zero_kernel<<<2 + (N + 255) / 256, 256>>>(Wm, attn_l, attn_r, N);
    // 1. elr + hist (independent)
    int ELR_B = (N * 32 + 255) / 256;
    int HIST_B = (E + 255) / 256;
    elr_hist_kernel<<<ELR_B + HIST_B, 256>>>(feat, dst, N, E, ELR_B);
    // 2. scan (2 launches) + scatter
    part_sum_kernel<<<NB, SCAN_BLK>>>(N);
    offsets_kernel<<<NB, SCAN_BLK>>>(N, E, NB);
    scatter_kernel<<<(E + 255) / 256, 256>>>(src, dst, E);
    // 3. softmax + agg_ori aggregation
    agg_kernel<<<(N * 32 + 255) / 256, 256>>>(feat, N);
    // 4. fused tail: rst GEMM + edge output (edge-balanced, coalesced layout)
    int GB = ((N + 63) / 64) * 4;
    int NW = (E + EPW - 1) / EPW;              // edge warps
    int EB = (NW * 32 + 255) / 256;
    tail_kernel<<<GB + EB, 256>>>(Wm, out, out + (size_t)N * HF, N, E, GB);
}

// round 15
// speedup vs baseline: 1.5355x; 1.1136x over previous
#include <cuda_runtime.h>
#include <cuda_bf16.h>
#include <cuda_fp16.h>
#include <math.h>

// Problem constants (fixed by the dataset)
#define MAXN 25000
#define MAXE 400000
#define IN_DIM 128
#define H_DIM 4
#define F_DIM 64
#define HF 256          // H*F
#define HIN 512         // H*IN

#define NEG_SLOPE 0.2f
#define SCAN_BLK 256

// ---------------- device scratch (no allocations allowed) ----------------
__device__ __align__(16) float g_wl[H_DIM * IN_DIM];   // folded attn_l @ W
__device__ __align__(16) float g_wr[H_DIM * IN_DIM];   // folded attn_r @ W
__device__ __align__(16) float g_el[MAXN * H_DIM];
__device__ __align__(16) float g_er[MAXN * H_DIM];
__device__ __align__(16) __half g_aggh[(size_t)MAXN * HIN];   // 25.6 MB fp16 agg
__device__ int       g_count[MAXN];
__device__ int       g_off[MAXN + 1];
__device__ int       g_cursor[MAXN];
__device__ long long g_es[MAXE];     // packed (src<<32 | eid) in CSR order
__device__ int       g_part[(MAXN + SCAN_BLK - 1) / SCAN_BLK + 1];

__device__ __forceinline__ float lrelu(float x) {
    return x > 0.0f ? x : NEG_SLOPE * x;
}

// ---------------- 0. prep (fold attn into W) + zero counts ------------------
__global__ void prep_zero_kernel(const float* __restrict__ Wm,
                                 const float* __restrict__ attn_l,
                                 const float* __restrict__ attn_r, int N)
{
    if (blockIdx.x < 2) {
        int t = blockIdx.x * 256 + threadIdx.x;   // 0..511
        if (t >= H_DIM * IN_DIM) return;
        int h = t >> 7, i = t & 127;
        float sl = 0.f, sr = 0.f;
        const float* wbase = Wm + (size_t)h * F_DIM * IN_DIM + i;
#pragma unroll 16
        for (int f = 0; f < F_DIM; f++) {
            float w = wbase[(size_t)f * IN_DIM];
            sl += attn_l[h * F_DIM + f] * w;
            sr += attn_r[h * F_DIM + f] * w;
        }
        g_wl[t] = sl;
        g_wr[t] = sr;
    } else {
        int i = (blockIdx.x - 2) * 256 + threadIdx.x;
        if (i < N) g_count[i] = 0;
    }
}

// ---------------- 1. el/er per node + dst histogram (independent works) ------
__global__ void elr_hist_kernel(const float* __restrict__ feat,
                                const int* __restrict__ dst,
                                int N, int E, int ELR_B)
{
    if (blockIdx.x < ELR_B) {
        int w = (blockIdx.x * blockDim.x + threadIdx.x) >> 5;
        int lane = threadIdx.x & 31;
        if (w >= N) return;
        float4 fv = *(const float4*)&feat[(size_t)w * IN_DIM + lane * 4];
        float sl[4], sr[4];
#pragma unroll
        for (int h = 0; h < 4; h++) {
            float4 a = *(const float4*)&g_wl[h * IN_DIM + lane * 4];
            float4 b = *(const float4*)&g_wr[h * IN_DIM + lane * 4];
            sl[h] = fv.x * a.x + fv.y * a.y + fv.z * a.z + fv.w * a.w;
            sr[h] = fv.x * b.x + fv.y * b.y + fv.z * b.z + fv.w * b.w;
        }
#pragma unroll
        for (int o = 16; o; o >>= 1) {
#pragma unroll
            for (int h = 0; h < 4; h++) {
                sl[h] += __shfl_xor_sync(0xffffffffu, sl[h], o);
                sr[h] += __shfl_xor_sync(0xffffffffu, sr[h], o);
            }
        }
        if (lane == 0) {
            *(float4*)&g_el[w * 4] = make_float4(sl[0], sl[1], sl[2], sl[3]);
            *(float4*)&g_er[w * 4] = make_float4(sr[0], sr[1], sr[2], sr[3]);
        }
    } else {
        int e = (blockIdx.x - ELR_B) * blockDim.x + threadIdx.x;
        if (e < E) atomicAdd(&g_count[dst[e]], 1);
    }
}

// ---------------- 2. hierarchical scan (2 kernels) + scatter -----------------
__global__ void part_sum_kernel(int N) {
    __shared__ int sh[SCAN_BLK];
    int i = blockIdx.x * SCAN_BLK + threadIdx.x;
    sh[threadIdx.x] = (i < N) ? g_count[i] : 0;
    __syncthreads();
#pragma unroll
    for (int d = SCAN_BLK / 2; d; d >>= 1) {
        if (threadIdx.x < d) sh[threadIdx.x] += sh[threadIdx.x + d];
        __syncthreads();
    }
    if (threadIdx.x == 0) g_part[blockIdx.x] = sh[0];
}
__global__ void offsets_kernel(int N, int E, int NB) {
    __shared__ int part[128];
    __shared__ int sh[SCAN_BLK];
    int t = threadIdx.x;
    if (t < 128) part[t] = (t < NB) ? g_part[t] : 0;
    __syncthreads();
    for (int d = 1; d < 128; d <<= 1) {
        int u = (t < 128 && t >= d) ? part[t - d] : 0;
        __syncthreads();
        if (t < 128) part[t] += u;
        __syncthreads();
    }
    int base = (blockIdx.x == 0) ? 0 : part[blockIdx.x - 1];

    int i = blockIdx.x * SCAN_BLK + t;
    int v = (i < N) ? g_count[i] : 0;
    sh[t] = v;
    __syncthreads();
    for (int d = 1; d < SCAN_BLK; d <<= 1) {
        int u = (t >= d) ? sh[t - d] : 0;
        __syncthreads();
        sh[t] += u;
        __syncthreads();
    }
    int off = base + sh[t] - v;
    if (i < N) { g_off[i] = off; g_cursor[i] = off; }
    if (blockIdx.x == 0 && t == 0) g_off[N] = E;
}
__global__ void scatter_kernel(const int* __restrict__ src,
                               const int* __restrict__ dst, int E) {
    int e = blockIdx.x * blockDim.x + threadIdx.x;
    if (e < E) {
        int s = src[e];
        int pos = atomicAdd(&g_cursor[dst[e]], 1);
        g_es[pos] = ((long long)s << 32) | (unsigned)e;
    }
}

// ---------------- 3. per-dst-node softmax + agg_ori aggregation --------------
// Writes ONLY the fp16 g_aggh (all downstream consumers read fp16).
__global__ __launch_bounds__(256) void agg_kernel(
    const float* __restrict__ feat, int N)
{
    int w = (blockIdx.x * blockDim.x + threadIdx.x) >> 5;
    int lane = threadIdx.x & 31;
    if (w >= N) return;
    int n = w;
    int start = g_off[n];
    int deg = g_off[n + 1] - start;

    if (deg == 0) {
#pragma unroll
        for (int h = 0; h < H_DIM; h++)
            *(uint2*)&g_aggh[(size_t)n * HIN + h * IN_DIM + lane * 4] =
                make_uint2(0u, 0u);
        return;
    }

    float4 er4 = *(const float4*)&g_er[n * 4];

    int mysrc = 0;
    float e0 = -1e30f, e1 = -1e30f, e2 = -1e30f, e3 = -1e30f;
    if (lane < deg) {
        mysrc = (int)(g_es[start + lane] >> 32);
        float4 el4 = *(const float4*)&g_el[mysrc * 4];
        e0 = lrelu(el4.x + er4.x); e1 = lrelu(el4.y + er4.y);
        e2 = lrelu(el4.z + er4.z); e3 = lrelu(el4.w + er4.w);
    }
    float m0 = e0, m1 = e1, m2 = e2, m3 = e3;
    for (int j = 32 + lane; j < deg; j += 32) {
        int s = (int)(g_es[start + j] >> 32);
        float4 el4 = *(const float4*)&g_el[s * 4];
        m0 = fmaxf(m0, lrelu(el4.x + er4.x)); m1 = fmaxf(m1, lrelu(el4.y + er4.y));
        m2 = fmaxf(m2, lrelu(el4.z + er4.z)); m3 = fmaxf(m3, lrelu(el4.w + er4.w));
    }
#pragma unroll
    for (int o = 16; o; o >>= 1) {
        m0 = fmaxf(m0, __shfl_xor_sync(0xffffffffu, m0, o));
        m1 = fmaxf(m1, __shfl_xor_sync(0xffffffffu, m1, o));
        m2 = fmaxf(m2, __shfl_xor_sync(0xffffffffu, m2, o));
        m3 = fmaxf(m3, __shfl_xor_sync(0xffffffffu, m3, o));
    }

    float aO[4][4] = {};
    float s0 = 0.f, s1 = 0.f, s2 = 0.f, s3 = 0.f;

    int dmain = min(deg, 32);
    int sj = __shfl_sync(0xffffffffu, mysrc, 0);
    float4 fv_n = *(const float4*)&feat[(size_t)sj * IN_DIM + lane * 4];
    for (int j = 0; j < dmain; j++) {
        float4 fv = fv_n;
        if (j + 1 < dmain) {
            int sn = __shfl_sync(0xffffffffu, mysrc, j + 1);
            fv_n = *(const float4*)&feat[(size_t)sn * IN_DIM + lane * 4];
        }
        float ex0 = __expf(__shfl_sync(0xffffffffu, e0, j) - m0);
        float ex1 = __expf(__shfl_sync(0xffffffffu, e1, j) - m1);
        float ex2 = __expf(__shfl_sync(0xffffffffu, e2, j) - m2);
        float ex3 = __expf(__shfl_sync(0xffffffffu, e3, j) - m3);
        s0 += ex0; s1 += ex1; s2 += ex2; s3 += ex3;
        aO[0][0] += ex0 * fv.x; aO[0][1] += ex0 * fv.y; aO[0][2] += ex0 * fv.z; aO[0][3] += ex0 * fv.w;
        aO[1][0] += ex1 * fv.x; aO[1][1] += ex1 * fv.y; aO[1][2] += ex1 * fv.z; aO[1][3] += ex1 * fv.w;
        aO[2][0] += ex2 * fv.x; aO[2][1] += ex2 * fv.y; aO[2][2] += ex2 * fv.z; aO[2][3] += ex2 * fv.w;
        aO[3][0] += ex3 * fv.x; aO[3][1] += ex3 * fv.y; aO[3][2] += ex3 * fv.z; aO[3][3] += ex3 * fv.w;
    }
    for (int j = 32; j < deg; j++) {
        int s = (int)(g_es[start + j] >> 32);
        float4 el4 = *(const float4*)&g_el[s * 4];
        float ex0 = __expf(lrelu(el4.x + er4.x) - m0);
        float ex1 = __expf(lrelu(el4.y + er4.y) - m1);
        float ex2 = __expf(lrelu(el4.z + er4.z) - m2);
        float ex3 = __expf(lrelu(el4.w + er4.w) - m3);
        s0 += ex0; s1 += ex1; s2 += ex2; s3 += ex3;
        float4 fv = *(const float4*)&feat[(size_t)s * IN_DIM + lane * 4];
        aO[0][0] += ex0 * fv.x; aO[0][1] += ex0 * fv.y; aO[0][2] += ex0 * fv.z; aO[0][3] += ex0 * fv.w;
        aO[1][0] += ex1 * fv.x; aO[1][1] += ex1 * fv.y; aO[1][2] += ex1 * fv.z; aO[1][3] += ex1 * fv.w;
        aO[2][0] += ex2 * fv.x; aO[2][1] += ex2 * fv.y; aO[2][2] += ex2 * fv.z; aO[2][3] += ex2 * fv.w;
        aO[3][0] += ex3 * fv.x; aO[3][1] += ex3 * fv.y; aO[3][2] += ex3 * fv.z; aO[3][3] += ex3 * fv.w;
    }

    float inv[4] = { 1.0f / s0, 1.0f / s1, 1.0f / s2, 1.0f / s3 };
#pragma unroll
    for (int h = 0; h < 4; h++) {
        __half2 h01 = __floats2half2_rn(aO[h][0] * inv[h], aO[h][1] * inv[h]);
        __half2 h23 = __floats2half2_rn(aO[h][2] * inv[h], aO[h][3] * inv[h]);
        uint2 raw;
        raw.x = *(unsigned*)&h01;
        raw.y = *(unsigned*)&h23;
        *(uint2*)&g_aggh[(size_t)n * HIN + h * IN_DIM + lane * 4] = raw;
    }
}

// ---------------- 4. fused tail: rst GEMM blocks + edge_out blocks -----------
// GEMM A-tiles and edge dst/src rows all read the fp16 g_aggh (fp32 compute).
__global__ __launch_bounds__(256) void tail_kernel(
    const float* __restrict__ Wm, float* __restrict__ rst,
    float* __restrict__ out, int N, int GB)
{
    __shared__ float As[32][68];   // [k][node]
    __shared__ float Bs[32][68];   // [k][f]

    if (blockIdx.x < GB) {
        int t = threadIdx.x;
        int row0 = (blockIdx.x >> 2) * 64;
        int h = blockIdx.x & 3;
        int ty = t >> 4, tx = t & 15;
        float acc[4][4] = {};

        const __half* Arow = g_aggh + (size_t)h * IN_DIM;        // + n*HIN
        const float* Brow = Wm + (size_t)h * F_DIM * IN_DIM;     // + f*IN_DIM

        for (int kt = 0; kt < 4; kt++) {
#pragma unroll
            for (int i = 0; i < 2; i++) {
                int idx = t + i * 256;     // 0..511
                int r = idx >> 3;          // 0..63
                int k4 = idx & 7;          // 0..7
                int row = row0 + r;
                float4 v = make_float4(0.f, 0.f, 0.f, 0.f);
                if (row < N) {
                    uint2 raw = *(const uint2*)&Arow[(size_t)row * HIN + kt * 32 + k4 * 4];
                    float2 f01 = __half22float2(*(__half2*)&raw.x);
                    float2 f23 = __half22float2(*(__half2*)&raw.y);
                    v = make_float4(f01.x, f01.y, f23.x, f23.y);
                }
                As[k4 * 4 + 0][r] = v.x; As[k4 * 4 + 1][r] = v.y;
                As[k4 * 4 + 2][r] = v.z; As[k4 * 4 + 3][r] = v.w;
                float4 wv = *(const float4*)&Brow[(size_t)r * IN_DIM + kt * 32 + k4 * 4];
                Bs[k4 * 4 + 0][r] = wv.x; Bs[k4 * 4 + 1][r] = wv.y;
                Bs[k4 * 4 + 2][r] = wv.z; Bs[k4 * 4 + 3][r] = wv.w;
            }
            __syncthreads();
#pragma unroll 8
            for (int k = 0; k < 32; k++) {
                float4 a = *(const float4*)&As[k][ty * 4];
                float4 b = *(const float4*)&Bs[k][tx * 4];
                acc[0][0] += a.x * b.x; acc[0][1] += a.x * b.y; acc[0][2] += a.x * b.z; acc[0][3] += a.x * b.w;
                acc[1][0] += a.y * b.x; acc[1][1] += a.y * b.y; acc[1][2] += a.y * b.z; acc[1][3] += a.y * b.w;
                acc[2][0] += a.z * b.x; acc[2][1] += a.z * b.y; acc[2][2] += a.z * b.z; acc[2][3] += a.z * b.w;
                acc[3][0] += a.w * b.x; acc[3][1] += a.w * b.y; acc[3][2] += a.w * b.z; acc[3][3] += a.w * b.w;
            }
            __syncthreads();
        }
#pragma unroll
        for (int i = 0; i < 4; i++) {
            int row = row0 + ty * 4 + i;
            if (row < N) {
                float4 v = make_float4(fmaxf(acc[i][0], 0.f), fmaxf(acc[i][1], 0.f),
                                       fmaxf(acc[i][2], 0.f), fmaxf(acc[i][3], 0.f));
                __stcs((float4*)&rst[(size_t)row * HF + h * F_DIM + tx * 4], v);
            }
        }
        return;
    }

    // ---- edge_out part: one warp per dst node, fp16 dst + src rows ----
    int w = ((blockIdx.x - GB) * blockDim.x + threadIdx.x) >> 5;
    int lane = threadIdx.x & 31;
    if (w >= N) return;
    int start = g_off[w];
    int end = g_off[w + 1];
    if (start == end) return;

    float4 bd[4];
    {
        const uint2* ad = (const uint2*)&g_aggh[(size_t)w * HIN];
#pragma unroll
        for (int h = 0; h < 4; h++) {
            uint2 raw = ad[h * 32 + lane];
            float2 f01 = __half22float2(*(__half2*)&raw.x);
            float2 f23 = __half22float2(*(__half2*)&raw.y);
            bd[h] = make_float4(f01.x, f01.y, f23.x, f23.y);
        }
    }

    long long es = g_es[start];
    int eid = (int)es;
    int s = (int)(es >> 32);
    uint2 a[4];
    {
        const uint2* ash = (const uint2*)&g_aggh[(size_t)s * HIN];
#pragma unroll
        for (int h = 0; h < 4; h++) a[h] = ash[h * 32 + lane];
    }
    for (int p = start; p < end; p++) {
        int neid = 0;
        uint2 nx[4];
        if (p + 1 < end) {
            long long nes = g_es[p + 1];
            neid = (int)nes;
            int ns = (int)(nes >> 32);
            const uint2* asn = (const uint2*)&g_aggh[(size_t)ns * HIN];
#pragma unroll
            for (int h = 0; h < 4; h++) nx[h] = asn[h * 32 + lane];
        }
        float4* o = (float4*)&out[(size_t)eid * HIN];
#pragma unroll
        for (int h = 0; h < 4; h++) {
            float2 f01 = __half22float2(*(__half2*)&a[h].x);
            float2 f23 = __half22float2(*(__half2*)&a[h].y);
            float4 v = make_float4(fabsf(f01.x - bd[h].x), fabsf(f01.y - bd[h].y),
                                   fabsf(f23.x - bd[h].z), fabsf(f23.y - bd[h].w));
            __stcs(&o[h * 32 + lane], v);
        }
        eid = neid;
#pragma unroll
        for (int h = 0; h < 4; h++) a[h] = nx[h];
    }
}

// ---------------- launch -----------------------------------------------------
extern "C" void kernel_launch(void* const* d_in, const int* in_sizes, int n_in,
                              void* d_out, int out_size)
{
    const float* feat   = (const float*)d_in[0];
    const float* Wm     = (const float*)d_in[1];
    const float* attn_l = (const float*)d_in[2];
    const float* attn_r = (const float*)d_in[3];
    const int*   src    = (const int*)d_in[4];
    const int*   dst    = (const int*)d_in[5];
    int N = in_sizes[0] / IN_DIM;
    int E = in_sizes[4];
    float* out = (float*)d_out;
    int NB = (N + SCAN_BLK - 1) / SCAN_BLK;

    // 0. prep + zero counts
    prep_zero_kernel<<<2 + (N + 255) / 256, 256>>>(Wm, attn_l, attn_r, N);
    // 1. elr + hist (independent)
    int ELR_B = (N * 32 + 255) / 256;
    int HIST_B = (E + 255) / 256;
    elr_hist_kernel<<<ELR_B + HIST_B, 256>>>(feat, dst, N, E, ELR_B);
    // 2. scan (2 launches) + scatter
    part_sum_kernel<<<NB, SCAN_BLK>>>(N);
    offsets_kernel<<<NB, SCAN_BLK>>>(N, E, NB);
    scatter_kernel<<<(E + 255) / 256, 256>>>(src, dst, E);
    // 3. softmax + agg_ori aggregation (fp16 output only)
    agg_kernel<<<(N * 32 + 255) / 256, 256>>>(feat, N);
    // 4. fused tail: rst GEMM + edge output
    int GB = ((N + 63) / 64) * 4;
    int EB = (N * 32 + 255) / 256;
    tail_kernel<<<GB + EB, 256>>>(Wm, out, out + (size_t)N * HF, N, GB);
}

// round 16
// speedup vs baseline: 1.5930x; 1.0374x over previous
#include <cuda_runtime.h>
#include <cuda_bf16.h>
#include <cuda_fp16.h>
#include <math.h>

// Problem constants (fixed by the dataset)
#define MAXN 25000
#define MAXE 400000
#define IN_DIM 128
#define H_DIM 4
#define F_DIM 64
#define HF 256          // H*F
#define HIN 512         // H*IN

#define NEG_SLOPE 0.2f
#define SCAN_BLK 256

// ---------------- device scratch (no allocations allowed) ----------------
__device__ __align__(16) float g_wl[H_DIM * IN_DIM];   // folded attn_l @ W
__device__ __align__(16) float g_wr[H_DIM * IN_DIM];   // folded attn_r @ W
__device__ __align__(16) float g_el[MAXN * H_DIM];
__device__ __align__(16) float g_er[MAXN * H_DIM];
__device__ __align__(16) __half g_aggh[(size_t)MAXN * HIN];   // 25.6 MB fp16 agg
__device__ int       g_count[MAXN];      // zero-initialized at load; re-zeroed by tail
__device__ int       g_off[MAXN + 1];
__device__ int       g_cursor[MAXN];
__device__ long long g_es[MAXE];     // packed (src<<32 | eid) in CSR order
__device__ int       g_part[(MAXN + SCAN_BLK - 1) / SCAN_BLK + 1];

__device__ __forceinline__ float lrelu(float x) {
    return x > 0.0f ? x : NEG_SLOPE * x;
}

// ---------------- 0. prep: fold attn vectors into W -------------------------
__global__ void prep_kernel(const float* __restrict__ Wm,
                            const float* __restrict__ attn_l,
                            const float* __restrict__ attn_r)
{
    int t = blockIdx.x * 256 + threadIdx.x;   // 0..511
    if (t >= H_DIM * IN_DIM) return;
    int h = t >> 7, i = t & 127;
    float sl = 0.f, sr = 0.f;
    const float* wbase = Wm + (size_t)h * F_DIM * IN_DIM + i;
#pragma unroll 16
    for (int f = 0; f < F_DIM; f++) {
        float w = wbase[(size_t)f * IN_DIM];
        sl += attn_l[h * F_DIM + f] * w;
        sr += attn_r[h * F_DIM + f] * w;
    }
    g_wl[t] = sl;
    g_wr[t] = sr;
}

// ---------------- 1. el/er per node + dst histogram (independent works) ------
// g_count arrives zeroed (module-load init on run 1, tail re-zero thereafter).
__global__ void elr_hist_kernel(const float* __restrict__ feat,
                                const int* __restrict__ dst,
                                int N, int E, int ELR_B)
{
    if (blockIdx.x < ELR_B) {
        int w = (blockIdx.x * blockDim.x + threadIdx.x) >> 5;
        int lane = threadIdx.x & 31;
        if (w >= N) return;
        float4 fv = *(const float4*)&feat[(size_t)w * IN_DIM + lane * 4];
        float sl[4], sr[4];
#pragma unroll
        for (int h = 0; h < 4; h++) {
            float4 a = *(const float4*)&g_wl[h * IN_DIM + lane * 4];
            float4 b = *(const float4*)&g_wr[h * IN_DIM + lane * 4];
            sl[h] = fv.x * a.x + fv.y * a.y + fv.z * a.z + fv.w * a.w;
            sr[h] = fv.x * b.x + fv.y * b.y + fv.z * b.z + fv.w * b.w;
        }
#pragma unroll
        for (int o = 16; o; o >>= 1) {
#pragma unroll
            for (int h = 0; h < 4; h++) {
                sl[h] += __shfl_xor_sync(0xffffffffu, sl[h], o);
                sr[h] += __shfl_xor_sync(0xffffffffu, sr[h], o);
            }
        }
        if (lane == 0) {
            *(float4*)&g_el[w * 4] = make_float4(sl[0], sl[1], sl[2], sl[3]);
            *(float4*)&g_er[w * 4] = make_float4(sr[0], sr[1], sr[2], sr[3]);
        }
    } else {
        int e = (blockIdx.x - ELR_B) * blockDim.x + threadIdx.x;
        if (e < E) atomicAdd(&g_count[dst[e]], 1);
    }
}

// ---------------- 2. hierarchical scan (2 kernels) + scatter -----------------
__global__ void part_sum_kernel(int N) {
    __shared__ int sh[SCAN_BLK];
    int i = blockIdx.x * SCAN_BLK + threadIdx.x;
    sh[threadIdx.x] = (i < N) ? g_count[i] : 0;
    __syncthreads();
#pragma unroll
    for (int d = SCAN_BLK / 2; d; d >>= 1) {
        if (threadIdx.x < d) sh[threadIdx.x] += sh[threadIdx.x + d];
        __syncthreads();
    }
    if (threadIdx.x == 0) g_part[blockIdx.x] = sh[0];
}
__global__ void offsets_kernel(int N, int E, int NB) {
    __shared__ int part[128];
    __shared__ int sh[SCAN_BLK];
    int t = threadIdx.x;
    if (t < 128) part[t] = (t < NB) ? g_part[t] : 0;
    __syncthreads();
    for (int d = 1; d < 128; d <<= 1) {
        int u = (t < 128 && t >= d) ? part[t - d] : 0;
        __syncthreads();
        if (t < 128) part[t] += u;
        __syncthreads();
    }
    int base = (blockIdx.x == 0) ? 0 : part[blockIdx.x - 1];

    int i = blockIdx.x * SCAN_BLK + t;
    int v = (i < N) ? g_count[i] : 0;
    sh[t] = v;
    __syncthreads();
    for (int d = 1; d < SCAN_BLK; d <<= 1) {
        int u = (t >= d) ? sh[t - d] : 0;
        __syncthreads();
        sh[t] += u;
        __syncthreads();
    }
    int off = base + sh[t] - v;
    if (i < N) { g_off[i] = off; g_cursor[i] = off; }
    if (blockIdx.x == 0 && t == 0) g_off[N] = E;
}
__global__ void scatter_kernel(const int* __restrict__ src,
                               const int* __restrict__ dst, int E) {
    int e = blockIdx.x * blockDim.x + threadIdx.x;
    if (e < E) {
        int s = src[e];
        int pos = atomicAdd(&g_cursor[dst[e]], 1);
        g_es[pos] = ((long long)s << 32) | (unsigned)e;
    }
}

// ---------------- 3. per-dst-node softmax + agg_ori aggregation --------------
// Writes ONLY the fp16 g_aggh (all downstream consumers read fp16).
__global__ __launch_bounds__(256) void agg_kernel(
    const float* __restrict__ feat, int N)
{
    int w = (blockIdx.x * blockDim.x + threadIdx.x) >> 5;
    int lane = threadIdx.x & 31;
    if (w >= N) return;
    int n = w;
    int start = g_off[n];
    int deg = g_off[n + 1] - start;

    if (deg == 0) {
#pragma unroll
        for (int h = 0; h < H_DIM; h++)
            *(uint2*)&g_aggh[(size_t)n * HIN + h * IN_DIM + lane * 4] =
                make_uint2(0u, 0u);
        return;
    }

    float4 er4 = *(const float4*)&g_er[n * 4];

    int mysrc = 0;
    float e0 = -1e30f, e1 = -1e30f, e2 = -1e30f, e3 = -1e30f;
    if (lane < deg) {
        mysrc = (int)(g_es[start + lane] >> 32);
        float4 el4 = *(const float4*)&g_el[mysrc * 4];
        e0 = lrelu(el4.x + er4.x); e1 = lrelu(el4.y + er4.y);
        e2 = lrelu(el4.z + er4.z); e3 = lrelu(el4.w + er4.w);
    }
    float m0 = e0, m1 = e1, m2 = e2, m3 = e3;
    for (int j = 32 + lane; j < deg; j += 32) {
        int s = (int)(g_es[start + j] >> 32);
        float4 el4 = *(const float4*)&g_el[s * 4];
        m0 = fmaxf(m0, lrelu(el4.x + er4.x)); m1 = fmaxf(m1, lrelu(el4.y + er4.y));
        m2 = fmaxf(m2, lrelu(el4.z + er4.z)); m3 = fmaxf(m3, lrelu(el4.w + er4.w));
    }
#pragma unroll
    for (int o = 16; o; o >>= 1) {
        m0 = fmaxf(m0, __shfl_xor_sync(0xffffffffu, m0, o));
        m1 = fmaxf(m1, __shfl_xor_sync(0xffffffffu, m1, o));
        m2 = fmaxf(m2, __shfl_xor_sync(0xffffffffu, m2, o));
        m3 = fmaxf(m3, __shfl_xor_sync(0xffffffffu, m3, o));
    }

    float aO[4][4] = {};
    float s0 = 0.f, s1 = 0.f, s2 = 0.f, s3 = 0.f;

    int dmain = min(deg, 32);
    int sj = __shfl_sync(0xffffffffu, mysrc, 0);
    float4 fv_n = *(const float4*)&feat[(size_t)sj * IN_DIM + lane * 4];
    for (int j = 0; j < dmain; j++) {
        float4 fv = fv_n;
        if (j + 1 < dmain) {
            int sn = __shfl_sync(0xffffffffu, mysrc, j + 1);
            fv_n = *(const float4*)&feat[(size_t)sn * IN_DIM + lane * 4];
        }
        float ex0 = __expf(__shfl_sync(0xffffffffu, e0, j) - m0);
        float ex1 = __expf(__shfl_sync(0xffffffffu, e1, j) - m1);
        float ex2 = __expf(__shfl_sync(0xffffffffu, e2, j) - m2);
        float ex3 = __expf(__shfl_sync(0xffffffffu, e3, j) - m3);
        s0 += ex0; s1 += ex1; s2 += ex2; s3 += ex3;
        aO[0][0] += ex0 * fv.x; aO[0][1] += ex0 * fv.y; aO[0][2] += ex0 * fv.z; aO[0][3] += ex0 * fv.w;
        aO[1][0] += ex1 * fv.x; aO[1][1] += ex1 * fv.y; aO[1][2] += ex1 * fv.z; aO[1][3] += ex1 * fv.w;
        aO[2][0] += ex2 * fv.x; aO[2][1] += ex2 * fv.y; aO[2][2] += ex2 * fv.z; aO[2][3] += ex2 * fv.w;
        aO[3][0] += ex3 * fv.x; aO[3][1] += ex3 * fv.y; aO[3][2] += ex3 * fv.z; aO[3][3] += ex3 * fv.w;
    }
    for (int j = 32; j < deg; j++) {
        int s = (int)(g_es[start + j] >> 32);
        float4 el4 = *(const float4*)&g_el[s * 4];
        float ex0 = __expf(lrelu(el4.x + er4.x) - m0);
        float ex1 = __expf(lrelu(el4.y + er4.y) - m1);
        float ex2 = __expf(lrelu(el4.z + er4.z) - m2);
        float ex3 = __expf(lrelu(el4.w + er4.w) - m3);
        s0 += ex0; s1 += ex1; s2 += ex2; s3 += ex3;
        float4 fv = *(const float4*)&feat[(size_t)s * IN_DIM + lane * 4];
        aO[0][0] += ex0 * fv.x; aO[0][1] += ex0 * fv.y; aO[0][2] += ex0 * fv.z; aO[0][3] += ex0 * fv.w;
        aO[1][0] += ex1 * fv.x; aO[1][1] += ex1 * fv.y; aO[1][2] += ex1 * fv.z; aO[1][3] += ex1 * fv.w;
        aO[2][0] += ex2 * fv.x; aO[2][1] += ex2 * fv.y; aO[2][2] += ex2 * fv.z; aO[2][3] += ex2 * fv.w;
        aO[3][0] += ex3 * fv.x; aO[3][1] += ex3 * fv.y; aO[3][2] += ex3 * fv.z; aO[3][3] += ex3 * fv.w;
    }

    float inv[4] = { 1.0f / s0, 1.0f / s1, 1.0f / s2, 1.0f / s3 };
#pragma unroll
    for (int h = 0; h < 4; h++) {
        __half2 h01 = __floats2half2_rn(aO[h][0] * inv[h], aO[h][1] * inv[h]);
        __half2 h23 = __floats2half2_rn(aO[h][2] * inv[h], aO[h][3] * inv[h]);
        uint2 raw;
        raw.x = *(unsigned*)&h01;
        raw.y = *(unsigned*)&h23;
        *(uint2*)&g_aggh[(size_t)n * HIN + h * IN_DIM + lane * 4] = raw;
    }
}

// ---------------- 4. fused tail: edge_out blocks first, rst GEMM last --------
// Edge blocks [0, EB) run first; GEMM blocks [EB, EB+GB) back-fill the uneven
// edge drain. GEMM blocks also re-zero g_count for the next graph replay.
__global__ __launch_bounds__(256) void tail_kernel(
    const float* __restrict__ Wm, float* __restrict__ rst,
    float* __restrict__ out, int N, int EB)
{
    __shared__ float As[32][68];   // [k][node]
    __shared__ float Bs[32][68];   // [k][f]

    if (blockIdx.x >= EB) {
        int gb = blockIdx.x - EB;
        int t = threadIdx.x;
        // re-zero g_count for next replay (consumed by part_sum long ago)
        int zi = gb * 256 + t;
        if (zi < N) g_count[zi] = 0;

        int row0 = (gb >> 2) * 64;
        int h = gb & 3;
        int ty = t >> 4, tx = t & 15;
        float acc[4][4] = {};

        const __half* Arow = g_aggh + (size_t)h * IN_DIM;        // + n*HIN
        const float* Brow = Wm + (size_t)h * F_DIM * IN_DIM;     // + f*IN_DIM

        for (int kt = 0; kt < 4; kt++) {
#pragma unroll
            for (int i = 0; i < 2; i++) {
                int idx = t + i * 256;     // 0..511
                int r = idx >> 3;          // 0..63
                int k4 = idx & 7;          // 0..7
                int row = row0 + r;
                float4 v = make_float4(0.f, 0.f, 0.f, 0.f);
                if (row < N) {
                    uint2 raw = *(const uint2*)&Arow[(size_t)row * HIN + kt * 32 + k4 * 4];
                    float2 f01 = __half22float2(*(__half2*)&raw.x);
                    float2 f23 = __half22float2(*(__half2*)&raw.y);
                    v = make_float4(f01.x, f01.y, f23.x, f23.y);
                }
                As[k4 * 4 + 0][r] = v.x; As[k4 * 4 + 1][r] = v.y;
                As[k4 * 4 + 2][r] = v.z; As[k4 * 4 + 3][r] = v.w;
                float4 wv = *(const float4*)&Brow[(size_t)r * IN_DIM + kt * 32 + k4 * 4];
                Bs[k4 * 4 + 0][r] = wv.x; Bs[k4 * 4 + 1][r] = wv.y;
                Bs[k4 * 4 + 2][r] = wv.z; Bs[k4 * 4 + 3][r] = wv.w;
            }
            __syncthreads();
#pragma unroll 8
            for (int k = 0; k < 32; k++) {
                float4 a = *(const float4*)&As[k][ty * 4];
                float4 b = *(const float4*)&Bs[k][tx * 4];
                acc[0][0] += a.x * b.x; acc[0][1] += a.x * b.y; acc[0][2] += a.x * b.z; acc[0][3] += a.x * b.w;
                acc[1][0] += a.y * b.x; acc[1][1] += a.y * b.y; acc[1][2] += a.y * b.z; acc[1][3] += a.y * b.w;
                acc[2][0] += a.z * b.x; acc[2][1] += a.z * b.y; acc[2][2] += a.z * b.z; acc[2][3] += a.z * b.w;
                acc[3][0] += a.w * b.x; acc[3][1] += a.w * b.y; acc[3][2] += a.w * b.z; acc[3][3] += a.w * b.w;
            }
            __syncthreads();
        }
#pragma unroll
        for (int i = 0; i < 4; i++) {
            int row = row0 + ty * 4 + i;
            if (row < N) {
                float4 v = make_float4(fmaxf(acc[i][0], 0.f), fmaxf(acc[i][1], 0.f),
                                       fmaxf(acc[i][2], 0.f), fmaxf(acc[i][3], 0.f));
                __stcs((float4*)&rst[(size_t)row * HF + h * F_DIM + tx * 4], v);
            }
        }
        return;
    }

    // ---- edge_out part: one warp per dst node, fp16 dst + src rows ----
    int w = (blockIdx.x * blockDim.x + threadIdx.x) >> 5;
    int lane = threadIdx.x & 31;
    if (w >= N) return;
    int start = g_off[w];
    int end = g_off[w + 1];
    if (start == end) return;

    float4 bd[4];
    {
        const uint2* ad = (const uint2*)&g_aggh[(size_t)w * HIN];
#pragma unroll
        for (int h = 0; h < 4; h++) {
            uint2 raw = ad[h * 32 + lane];
            float2 f01 = __half22float2(*(__half2*)&raw.x);
            float2 f23 = __half22float2(*(__half2*)&raw.y);
            bd[h] = make_float4(f01.x, f01.y, f23.x, f23.y);
        }
    }

    long long es = g_es[start];
    int eid = (int)es;
    int s = (int)(es >> 32);
    uint2 a[4];
    {
        const uint2* ash = (const uint2*)&g_aggh[(size_t)s * HIN];
#pragma unroll
        for (int h = 0; h < 4; h++) a[h] = ash[h * 32 + lane];
    }
    for (int p = start; p < end; p++) {
        int neid = 0;
        uint2 nx[4];
        if (p + 1 < end) {
            long long nes = g_es[p + 1];
            neid = (int)nes;
            int ns = (int)(nes >> 32);
            const uint2* asn = (const uint2*)&g_aggh[(size_t)ns * HIN];
#pragma unroll
            for (int h = 0; h < 4; h++) nx[h] = asn[h * 32 + lane];
        }
        float4* o = (float4*)&out[(size_t)eid * HIN];
#pragma unroll
        for (int h = 0; h < 4; h++) {
            float2 f01 = __half22float2(*(__half2*)&a[h].x);
            float2 f23 = __half22float2(*(__half2*)&a[h].y);
            float4 v = make_float4(fabsf(f01.x - bd[h].x), fabsf(f01.y - bd[h].y),
                                   fabsf(f23.x - bd[h].z), fabsf(f23.y - bd[h].w));
            __stcs(&o[h * 32 + lane], v);
        }
        eid = neid;
#pragma unroll
        for (int h = 0; h < 4; h++) a[h] = nx[h];
    }
}

// ---------------- launch -----------------------------------------------------
extern "C" void kernel_launch(void* const* d_in, const int* in_sizes, int n_in,
                              void* d_out, int out_size)
{
    const float* feat   = (const float*)d_in[0];
    const float* Wm     = (const float*)d_in[1];
    const float* attn_l = (const float*)d_in[2];
    const float* attn_r = (const float*)d_in[3];
    const int*   src    = (const int*)d_in[4];
    const int*   dst    = (const int*)d_in[5];
    int N = in_sizes[0] / IN_DIM;
    int E = in_sizes[4];
    float* out = (float*)d_out;
    int NB = (N + SCAN_BLK - 1) / SCAN_BLK;

    // 0. prep (wl/wr fold only; g_count zeroed by previous tail / load init)
    prep_kernel<<<2, 256>>>(Wm, attn_l, attn_r);
    // 1. elr + hist (independent)
    int ELR_B = (N * 32 + 255) / 256;
    int HIST_B = (E + 255) / 256;
    elr_hist_kernel<<<ELR_B + HIST_B, 256>>>(feat, dst, N, E, ELR_B);
    // 2. scan (2 launches) + scatter
    part_sum_kernel<<<NB, SCAN_BLK>>>(N);
    offsets_kernel<<<NB, SCAN_BLK>>>(N, E, NB);
    scatter_kernel<<<(E + 255) / 256, 256>>>(src, dst, E);
    // 3. softmax + agg_ori aggregation (fp16 output only)
    agg_kernel<<<(N * 32 + 255) / 256, 256>>>(feat, N);
    // 4. fused tail: edge blocks first, GEMM blocks last (drain-fill + re-zero)
    int GB = ((N + 63) / 64) * 4;
    int EB = (N * 32 + 255) / 256;
    tail_kernel<<<EB + GB, 256>>>(Wm, out, out + (size_t)N * HF, N, EB);
}